// round 1
// baseline (speedup 1.0000x reference)
#include <cuda_runtime.h>
#include <math.h>

// Problem dims
#define NPIX (16*64*64)      // 65536 pixels
#define DIMC 512

// -------- scratch (device globals; no allocations allowed) --------
__device__ float g_t[NPIX*32];        // proj_in outputs: ch 0..15 = mh, 16..31 = mw
__device__ float g_mixed[NPIX*32];    // windowed-mixing outputs, same channel split
__device__ float g_h[NPIX*DIMC];
__device__ float g_w[NPIX*DIMC];
__device__ float g_c[NPIX*DIMC];
__device__ float g_part[1024*DIMC];   // per-block partial sums for the spatial mean
__device__ float g_a3[3*16*DIMC];     // softmax reweight coefficients

// ====================================================================
// K1: fused proj_in for both branches.
// t[p, 0:16] = x[p,:] @ mh_pin + b ; t[p,16:32] = x[p,:] @ mw_pin + b
// GEMM M=65536, N=32, K=512. Tile: 128 rows/block, full N, k-chunk 64.
// ====================================================================
__global__ __launch_bounds__(256) void k1_proj_in(
    const float* __restrict__ x,
    const float* __restrict__ w0, const float* __restrict__ b0,
    const float* __restrict__ w1, const float* __restrict__ b1)
{
    __shared__ float Xs[64][132];   // [k][row], padded
    __shared__ float Ws[64][32];    // [k][col]
    const int t = threadIdx.x;
    const int pbase = blockIdx.x * 128;
    const int p    = t >> 1;
    const int koff = (t & 1) * 32;
    const int tr = t >> 3;          // 0..31 -> rows tr*4..+3
    const int tc = t & 7;           // 0..7  -> cols tc*4..+3

    float4 acc0 = {0,0,0,0}, acc1 = {0,0,0,0}, acc2 = {0,0,0,0}, acc3 = {0,0,0,0};

    for (int kc = 0; kc < 512; kc += 64) {
        __syncthreads();
        #pragma unroll
        for (int i = 0; i < 8; i++) {
            float4 v = *(const float4*)(x + (size_t)(pbase + p) * 512 + kc + koff + i * 4);
            Xs[koff + i*4 + 0][p] = v.x;
            Xs[koff + i*4 + 1][p] = v.y;
            Xs[koff + i*4 + 2][p] = v.z;
            Xs[koff + i*4 + 3][p] = v.w;
        }
        #pragma unroll
        for (int i = 0; i < 8; i++) {
            int idx = t + i * 256;
            int k = idx >> 5, j = idx & 31;
            Ws[k][j] = (j < 16) ? w0[(kc + k) * 16 + j] : w1[(kc + k) * 16 + (j - 16)];
        }
        __syncthreads();
        #pragma unroll
        for (int kk = 0; kk < 64; kk++) {
            float4 av = *(const float4*)&Xs[kk][tr * 4];
            float4 bv = *(const float4*)&Ws[kk][tc * 4];
            acc0.x += av.x*bv.x; acc0.y += av.x*bv.y; acc0.z += av.x*bv.z; acc0.w += av.x*bv.w;
            acc1.x += av.y*bv.x; acc1.y += av.y*bv.y; acc1.z += av.y*bv.z; acc1.w += av.y*bv.w;
            acc2.x += av.z*bv.x; acc2.y += av.z*bv.y; acc2.z += av.z*bv.z; acc2.w += av.z*bv.w;
            acc3.x += av.w*bv.x; acc3.y += av.w*bv.y; acc3.z += av.w*bv.z; acc3.w += av.w*bv.w;
        }
    }
    float bb[4];
    #pragma unroll
    for (int j = 0; j < 4; j++) { int c = tc*4 + j; bb[j] = (c < 16) ? b0[c] : b1[c - 16]; }

    float4 o;
    o = make_float4(acc0.x+bb[0], acc0.y+bb[1], acc0.z+bb[2], acc0.w+bb[3]);
    *(float4*)(g_t + (size_t)(pbase + tr*4 + 0) * 32 + tc*4) = o;
    o = make_float4(acc1.x+bb[0], acc1.y+bb[1], acc1.z+bb[2], acc1.w+bb[3]);
    *(float4*)(g_t + (size_t)(pbase + tr*4 + 1) * 32 + tc*4) = o;
    o = make_float4(acc2.x+bb[0], acc2.y+bb[1], acc2.z+bb[2], acc2.w+bb[3]);
    *(float4*)(g_t + (size_t)(pbase + tr*4 + 2) * 32 + tc*4) = o;
    o = make_float4(acc3.x+bb[0], acc3.y+bb[1], acc3.z+bb[2], acc3.w+bb[3]);
    *(float4*)(g_t + (size_t)(pbase + tr*4 + 3) * 32 + tc*4) = o;
}

// ====================================================================
// K2: windowed mixing for both branches.
// Per (mix, head): 1024 windows, each out[f] = sum_d W[f,d]*v[d] + fb[f]
// with W[f,d] = full_w[f*1024 + head*128 + d].
// Window->pixel map (derived from einops chain, verified):
//  mix0 (H_sp=32,W_sp=2): d=(h,wsp,dd)=h*4+wsp*2+dd ; row=2h+n1 ; col=4*nw+2*wsp+n2
//  mix1 (H_sp=2,W_sp=32): d=hsp*64+wsp*2+dd ; row=4*nw+2*hsp+n1 ; col=2*wsp+n2
// Output f uses the identical (pixel, channel) map as input d.
// Block = (mix, head, 64-window tile). W cached in dynamic smem (66KB).
// ====================================================================
__global__ __launch_bounds__(128) void k2_mix(
    const float* __restrict__ fw0, const float* __restrict__ fb0,
    const float* __restrict__ fw1, const float* __restrict__ fb1)
{
    extern __shared__ float sm[];
    float (*Wsm)[129] = (float (*)[129])sm;          // [d][f], padded
    __shared__ float vst[128][4];                    // [d][window-of-4]

    const int mix  = blockIdx.x >> 7;
    const int head = (blockIdx.x >> 4) & 7;
    const int wt   = blockIdx.x & 15;
    const float* fw = mix ? fw1 : fw0;
    const float* fb = mix ? fb1 : fb0;
    const int t = threadIdx.x;   // == f == d lane

    for (int i = t; i < 128 * 128; i += 128) {
        int d = i & 127;
        int f = i >> 7;
        Wsm[d][f] = fw[f * 1024 + head * 128 + d];
    }
    const int ch = mix * 16 + head * 2 + (t & 1);
    const float fbv = fb[t];
    __syncthreads();

    for (int pass = 0; pass < 16; pass++) {
        int px[4];
        #pragma unroll
        for (int j = 0; j < 4; j++) {
            int wg = wt * 64 + pass * 4 + j;
            int Bb = wg >> 4, nw = wg & 15;
            int b = Bb >> 2, n1 = (Bb >> 1) & 1, n2 = Bb & 1;
            int row, col;
            if (mix == 0) { row = 2 * (t >> 2) + n1;        col = 4 * nw + 2 * ((t >> 1) & 1) + n2; }
            else          { row = 4 * nw + 2 * (t >> 6) + n1; col = 2 * ((t >> 1) & 31) + n2; }
            int pix = (b * 64 + row) * 64 + col;
            px[j] = pix;
            vst[t][j] = g_t[(size_t)pix * 32 + ch];
        }
        __syncthreads();
        float a0 = fbv, a1 = fbv, a2 = fbv, a3 = fbv;
        #pragma unroll 8
        for (int d = 0; d < 128; d++) {
            float4 vv = *(const float4*)&vst[d][0];
            float wv = Wsm[d][t];
            a0 += vv.x * wv; a1 += vv.y * wv; a2 += vv.z * wv; a3 += vv.w * wv;
        }
        g_mixed[(size_t)px[0] * 32 + ch] = a0;
        g_mixed[(size_t)px[1] * 32 + ch] = a1;
        g_mixed[(size_t)px[2] * 32 + ch] = a2;
        g_mixed[(size_t)px[3] * 32 + ch] = a3;
        __syncthreads();
    }
}

// ====================================================================
// K3: proj_out (both branches) + MixC + per-block partial sums of (h+w+c).
// Block = (batch b, 8x8 pixel tile), 512 threads = one channel each.
// All per-channel weights live in registers; mixed tile in smem.
// ====================================================================
__global__ __launch_bounds__(512) void k3_combine(
    const float* __restrict__ x,
    const float* __restrict__ pout0, const float* __restrict__ pb0,
    const float* __restrict__ pout1, const float* __restrict__ pb1,
    const float* __restrict__ cwg, const float* __restrict__ cbg)
{
    __shared__ float msm[64][32];
    const int bx = blockIdx.x;
    const int b = bx >> 6, tile = bx & 63;
    const int ty = tile >> 3, tx = tile & 7;
    const int ch = threadIdx.x;

    for (int i = threadIdx.x; i < 2048; i += 512) {
        int pix = i >> 5, cc = i & 31;
        int pr = pix >> 3, pc = pix & 7;
        msm[pix][cc] = g_mixed[(size_t)((b*64 + ty*8 + pr) * 64 + tx*8 + pc) * 32 + cc];
    }
    __syncthreads();

    float w0r[16], w1r[16], cwr[16], cbr[4];
    #pragma unroll
    for (int k = 0; k < 16; k++) { w0r[k] = pout0[k*512 + ch]; w1r[k] = pout1[k*512 + ch]; }
    #pragma unroll
    for (int i = 0; i < 16; i++) cwr[i] = cwg[ch*16 + i];
    #pragma unroll
    for (int p = 0; p < 4; p++) cbr[p] = cbg[ch*4 + p];
    const float hb = pb0[ch], wb = pb1[ch];

    float ssum = 0.f;
    for (int bi = 0; bi < 16; bi++) {
        int brow = bi >> 2, bcol = bi & 3;
        int r0 = ty*8 + brow*2, c0 = tx*8 + bcol*2;
        float x4[4];
        #pragma unroll
        for (int q = 0; q < 4; q++) {
            int q1 = q >> 1, q2 = q & 1;
            x4[q] = x[(size_t)((b*64 + r0 + q1) * 64 + c0 + q2) * 512 + ch];
        }
        #pragma unroll
        for (int p = 0; p < 4; p++) {
            int p1 = p >> 1, p2 = p & 1;
            int pix = (brow*2 + p1) * 8 + (bcol*2 + p2);
            float cv = cbr[p];
            #pragma unroll
            for (int q = 0; q < 4; q++) cv += x4[q] * cwr[q*4 + p];

            const float4* m4 = (const float4*)&msm[pix][0];
            float4 m0 = m4[0], m1 = m4[1], m2 = m4[2], m3 = m4[3];
            float hv = hb;
            hv += m0.x*w0r[0]  + m0.y*w0r[1]  + m0.z*w0r[2]  + m0.w*w0r[3];
            hv += m1.x*w0r[4]  + m1.y*w0r[5]  + m1.z*w0r[6]  + m1.w*w0r[7];
            hv += m2.x*w0r[8]  + m2.y*w0r[9]  + m2.z*w0r[10] + m2.w*w0r[11];
            hv += m3.x*w0r[12] + m3.y*w0r[13] + m3.z*w0r[14] + m3.w*w0r[15];
            float4 u0 = m4[4], u1 = m4[5], u2 = m4[6], u3 = m4[7];
            float wv = wb;
            wv += u0.x*w1r[0]  + u0.y*w1r[1]  + u0.z*w1r[2]  + u0.w*w1r[3];
            wv += u1.x*w1r[4]  + u1.y*w1r[5]  + u1.z*w1r[6]  + u1.w*w1r[7];
            wv += u2.x*w1r[8]  + u2.y*w1r[9]  + u2.z*w1r[10] + u2.w*w1r[11];
            wv += u3.x*w1r[12] + u3.y*w1r[13] + u3.z*w1r[14] + u3.w*w1r[15];

            size_t gp = (size_t)((b*64 + r0 + p1) * 64 + c0 + p2) * 512 + ch;
            g_h[gp] = hv; g_w[gp] = wv; g_c[gp] = cv;
            ssum += hv + wv + cv;
        }
    }
    g_part[(size_t)bx * 512 + ch] = ssum;
}

// ====================================================================
// K4: spatial-mean reduction + reweight MLP (exact gelu) + softmax-over-3.
// One block per batch element.
// ====================================================================
__global__ __launch_bounds__(128) void k4_reweight(
    const float* __restrict__ fc1w, const float* __restrict__ fc1b,
    const float* __restrict__ fc2w, const float* __restrict__ fc2b)
{
    __shared__ float asm_[512];
    __shared__ float hsm[128];
    __shared__ float fsm[1536];
    const int b = blockIdx.x;
    const int t = threadIdx.x;

    for (int c = t; c < 512; c += 128) {
        float s = 0.f;
        for (int tl = 0; tl < 64; tl++) s += g_part[(size_t)(b*64 + tl) * 512 + c];
        asm_[c] = s * (1.0f / 4096.0f);
    }
    __syncthreads();
    {
        float acc = fc1b[t];
        for (int k = 0; k < 512; k++) acc += asm_[k] * fc1w[k*128 + t];
        hsm[t] = 0.5f * acc * (1.0f + erff(acc * 0.70710678118654752f));
    }
    __syncthreads();
    for (int n = t; n < 1536; n += 128) {
        float acc = fc2b[n];
        for (int j = 0; j < 128; j++) acc += hsm[j] * fc2w[j*1536 + n];
        fsm[n] = acc;
    }
    __syncthreads();
    for (int c = t; c < 512; c += 128) {
        float v0 = fsm[c*3], v1 = fsm[c*3+1], v2 = fsm[c*3+2];
        float mx = fmaxf(v0, fmaxf(v1, v2));
        float e0 = expf(v0-mx), e1 = expf(v1-mx), e2 = expf(v2-mx);
        float inv = 1.0f / (e0 + e1 + e2);
        g_a3[(0*16 + b)*512 + c] = e0 * inv;
        g_a3[(1*16 + b)*512 + c] = e1 * inv;
        g_a3[(2*16 + b)*512 + c] = e2 * inv;
    }
}

// ====================================================================
// K5: final fused GEMM: out = (h*a0 + w*a1 + c*a2) @ proj_w + proj_b.
// M=65536, N=512, K=512. 128x128 tiles, k-chunk 16, 256 threads, 8x8/thread.
// A tile built on the fly from h/w/c with the per-(b,channel) softmax weights.
// ====================================================================
__global__ __launch_bounds__(256) void k5_final(
    const float* __restrict__ pw, const float* __restrict__ pb,
    float* __restrict__ out)
{
    __shared__ float As[16][132];
    __shared__ float Bs[16][132];
    __shared__ float a3s[3][512];

    const int t = threadIdx.x;
    const int mbase = blockIdx.x * 128;
    const int nbase = blockIdx.y * 128;
    const int b = mbase >> 12;           // 4096 pixels per batch, tiles never straddle

    for (int i = t; i < 1536; i += 256) {
        int which = i / 512, kk = i % 512;
        a3s[which][kk] = g_a3[(which*16 + b)*512 + kk];
    }

    const int tr = t >> 4, tc = t & 15;      // 16x16 thread grid, 8x8 each
    const int pA = t >> 1, kA = (t & 1) * 8; // A-tile loader coords
    const int kB = t >> 4, nB = (t & 15) * 8;// B-tile loader coords

    float acc[8][8];
    #pragma unroll
    for (int i = 0; i < 8; i++)
        #pragma unroll
        for (int j = 0; j < 8; j++) acc[i][j] = 0.f;

    __syncthreads();

    for (int k0 = 0; k0 < 512; k0 += 16) {
        __syncthreads();
        // A tile: combine h,w,c with reweight coefficients
        {
            const size_t base = (size_t)(mbase + pA) * 512 + k0 + kA;
            #pragma unroll
            for (int half = 0; half < 2; half++) {
                float4 hv = *(const float4*)(g_h + base + half*4);
                float4 wv = *(const float4*)(g_w + base + half*4);
                float4 cv = *(const float4*)(g_c + base + half*4);
                int kb = k0 + kA + half*4;
                As[kA + half*4 + 0][pA] = hv.x*a3s[0][kb+0] + wv.x*a3s[1][kb+0] + cv.x*a3s[2][kb+0];
                As[kA + half*4 + 1][pA] = hv.y*a3s[0][kb+1] + wv.y*a3s[1][kb+1] + cv.y*a3s[2][kb+1];
                As[kA + half*4 + 2][pA] = hv.z*a3s[0][kb+2] + wv.z*a3s[1][kb+2] + cv.z*a3s[2][kb+2];
                As[kA + half*4 + 3][pA] = hv.w*a3s[0][kb+3] + wv.w*a3s[1][kb+3] + cv.w*a3s[2][kb+3];
            }
        }
        // B tile
        #pragma unroll
        for (int half = 0; half < 2; half++) {
            float4 bv = *(const float4*)(pw + (size_t)(k0 + kB) * 512 + nbase + nB + half*4);
            *(float4*)&Bs[kB][nB + half*4] = bv;
        }
        __syncthreads();

        #pragma unroll
        for (int kk = 0; kk < 16; kk++) {
            float a_frag[8], b_frag[8];
            *(float4*)&a_frag[0] = *(const float4*)&As[kk][tr*8];
            *(float4*)&a_frag[4] = *(const float4*)&As[kk][tr*8 + 4];
            *(float4*)&b_frag[0] = *(const float4*)&Bs[kk][tc*8];
            *(float4*)&b_frag[4] = *(const float4*)&Bs[kk][tc*8 + 4];
            #pragma unroll
            for (int i = 0; i < 8; i++)
                #pragma unroll
                for (int j = 0; j < 8; j++)
                    acc[i][j] += a_frag[i] * b_frag[j];
        }
    }

    const int col0 = nbase + tc*8;
    float bias[8];
    #pragma unroll
    for (int j = 0; j < 8; j++) bias[j] = pb[col0 + j];
    #pragma unroll
    for (int i = 0; i < 8; i++) {
        size_t row = (size_t)(mbase + tr*8 + i);
        float4 o0 = make_float4(acc[i][0]+bias[0], acc[i][1]+bias[1], acc[i][2]+bias[2], acc[i][3]+bias[3]);
        float4 o1 = make_float4(acc[i][4]+bias[4], acc[i][5]+bias[5], acc[i][6]+bias[6], acc[i][7]+bias[7]);
        *(float4*)(out + row*512 + col0)     = o0;
        *(float4*)(out + row*512 + col0 + 4) = o1;
    }
}

// ====================================================================
extern "C" void kernel_launch(void* const* d_in, const int* in_sizes, int n_in,
                              void* d_out, int out_size)
{
    (void)in_sizes; (void)n_in; (void)out_size;
    const float* x       = (const float*)d_in[0];
    const float* mh_pinw = (const float*)d_in[1];
    const float* mh_pinb = (const float*)d_in[2];
    const float* mh_fw   = (const float*)d_in[3];
    const float* mh_fb   = (const float*)d_in[4];
    const float* mh_pow  = (const float*)d_in[5];
    const float* mh_pob  = (const float*)d_in[6];
    const float* mw_pinw = (const float*)d_in[7];
    const float* mw_pinb = (const float*)d_in[8];
    const float* mw_fw   = (const float*)d_in[9];
    const float* mw_fb   = (const float*)d_in[10];
    const float* mw_pow  = (const float*)d_in[11];
    const float* mw_pob  = (const float*)d_in[12];
    const float* c_w     = (const float*)d_in[13];
    const float* c_b     = (const float*)d_in[14];
    const float* fc1w    = (const float*)d_in[15];
    const float* fc1b    = (const float*)d_in[16];
    const float* fc2w    = (const float*)d_in[17];
    const float* fc2b    = (const float*)d_in[18];
    const float* projw   = (const float*)d_in[19];
    const float* projb   = (const float*)d_in[20];
    float* out = (float*)d_out;

    const int k2_smem = 128 * 129 * sizeof(float);  // 66048 B
    cudaFuncSetAttribute(k2_mix, cudaFuncAttributeMaxDynamicSharedMemorySize, k2_smem);

    k1_proj_in<<<512, 256>>>(x, mh_pinw, mh_pinb, mw_pinw, mw_pinb);
    k2_mix<<<256, 128, k2_smem>>>(mh_fw, mh_fb, mw_fw, mw_fb);
    k3_combine<<<1024, 512>>>(x, mh_pow, mh_pob, mw_pow, mw_pob, c_w, c_b);
    k4_reweight<<<16, 128>>>(fc1w, fc1b, fc2w, fc2b);
    k5_final<<<dim3(512, 4), 256>>>(projw, projb, out);
}

// round 2
// speedup vs baseline: 1.0284x; 1.0284x over previous
#include <cuda_runtime.h>
#include <math.h>

// Problem dims
#define NPIX (16*64*64)      // 65536 pixels
#define DIMC 512

// -------- scratch (device globals; no allocations allowed) --------
__device__ float g_t[NPIX*32];        // proj_in outputs: ch 0..15 = mh, 16..31 = mw
__device__ float g_mixed[NPIX*32];    // windowed-mixing outputs, same channel split
__device__ float g_h[NPIX*DIMC];
__device__ float g_w[NPIX*DIMC];
__device__ float g_c[NPIX*DIMC];
__device__ float g_part[1024*DIMC];   // per-block partial sums for the spatial mean
__device__ float g_mean[16*DIMC];
__device__ float g_hid[16*128];
__device__ float g_f[16*1536];
__device__ float g_a3[3*16*DIMC];     // softmax reweight coefficients

// packed fp32x2 FMA (Blackwell FFMA2 — only reachable via PTX)
#define FMA_F32X2(d, a, b, c) \
    asm("fma.rn.f32x2 %0, %1, %2, %3;" : "=l"(d) : "l"(a), "l"(b), "l"(c))
#define PACK2(d, f) \
    asm("mov.b64 %0, {%1, %1};" : "=l"(d) : "f"(f))
#define UNPACK2(lo, hi, v) \
    asm("mov.b64 {%0, %1}, %2;" : "=f"(lo), "=f"(hi) : "l"(v))

// ====================================================================
// K1: fused proj_in for both branches.  GEMM M=65536, N=32, K=512.
// 128 rows/block, k-chunk 64, packed f32x2 inner product.
// ====================================================================
__global__ __launch_bounds__(256) void k1_proj_in(
    const float* __restrict__ x,
    const float* __restrict__ w0, const float* __restrict__ b0,
    const float* __restrict__ w1, const float* __restrict__ b1)
{
    __shared__ float Xs[64][132];   // [k][row], padded
    __shared__ float Ws[64][32];    // [k][col]
    const int t = threadIdx.x;
    const int pbase = blockIdx.x * 128;
    const int p    = t >> 1;
    const int koff = (t & 1) * 32;
    const int tr = t >> 3;          // rows tr*4..+3
    const int tc = t & 7;           // cols tc*4..+3

    unsigned long long accp[4][2];
    #pragma unroll
    for (int r = 0; r < 4; r++) { accp[r][0] = 0ull; accp[r][1] = 0ull; }

    for (int kc = 0; kc < 512; kc += 64) {
        __syncthreads();
        #pragma unroll
        for (int i = 0; i < 8; i++) {
            float4 v = *(const float4*)(x + (size_t)(pbase + p) * 512 + kc + koff + i * 4);
            Xs[koff + i*4 + 0][p] = v.x;
            Xs[koff + i*4 + 1][p] = v.y;
            Xs[koff + i*4 + 2][p] = v.z;
            Xs[koff + i*4 + 3][p] = v.w;
        }
        #pragma unroll
        for (int i = 0; i < 8; i++) {
            int idx = t + i * 256;
            int k = idx >> 5, j = idx & 31;
            Ws[k][j] = (j < 16) ? w0[(kc + k) * 16 + j] : w1[(kc + k) * 16 + (j - 16)];
        }
        __syncthreads();
        #pragma unroll
        for (int kk = 0; kk < 64; kk++) {
            float4 av = *(const float4*)&Xs[kk][tr * 4];
            const unsigned long long* bp = (const unsigned long long*)&Ws[kk][tc * 4];
            unsigned long long b20 = bp[0], b21 = bp[1];
            unsigned long long aa;
            PACK2(aa, av.x); FMA_F32X2(accp[0][0], aa, b20, accp[0][0]); FMA_F32X2(accp[0][1], aa, b21, accp[0][1]);
            PACK2(aa, av.y); FMA_F32X2(accp[1][0], aa, b20, accp[1][0]); FMA_F32X2(accp[1][1], aa, b21, accp[1][1]);
            PACK2(aa, av.z); FMA_F32X2(accp[2][0], aa, b20, accp[2][0]); FMA_F32X2(accp[2][1], aa, b21, accp[2][1]);
            PACK2(aa, av.w); FMA_F32X2(accp[3][0], aa, b20, accp[3][0]); FMA_F32X2(accp[3][1], aa, b21, accp[3][1]);
        }
    }
    float bb[4];
    #pragma unroll
    for (int j = 0; j < 4; j++) { int c = tc*4 + j; bb[j] = (c < 16) ? b0[c] : b1[c - 16]; }

    #pragma unroll
    for (int r = 0; r < 4; r++) {
        float v0, v1, v2, v3;
        UNPACK2(v0, v1, accp[r][0]);
        UNPACK2(v2, v3, accp[r][1]);
        float4 o = make_float4(v0+bb[0], v1+bb[1], v2+bb[2], v3+bb[3]);
        *(float4*)(g_t + (size_t)(pbase + tr*4 + r) * 32 + tc*4) = o;
    }
}

// ====================================================================
// K2: windowed mixing for both branches (unchanged from R1).
// ====================================================================
__global__ __launch_bounds__(128) void k2_mix(
    const float* __restrict__ fw0, const float* __restrict__ fb0,
    const float* __restrict__ fw1, const float* __restrict__ fb1)
{
    extern __shared__ float sm[];
    float (*Wsm)[129] = (float (*)[129])sm;          // [d][f], padded
    __shared__ float vst[128][4];                    // [d][window-of-4]

    const int mix  = blockIdx.x >> 7;
    const int head = (blockIdx.x >> 4) & 7;
    const int wt   = blockIdx.x & 15;
    const float* fw = mix ? fw1 : fw0;
    const float* fb = mix ? fb1 : fb0;
    const int t = threadIdx.x;

    for (int i = t; i < 128 * 128; i += 128) {
        int d = i & 127;
        int f = i >> 7;
        Wsm[d][f] = fw[f * 1024 + head * 128 + d];
    }
    const int ch = mix * 16 + head * 2 + (t & 1);
    const float fbv = fb[t];
    __syncthreads();

    for (int pass = 0; pass < 16; pass++) {
        int px[4];
        #pragma unroll
        for (int j = 0; j < 4; j++) {
            int wg = wt * 64 + pass * 4 + j;
            int Bb = wg >> 4, nw = wg & 15;
            int b = Bb >> 2, n1 = (Bb >> 1) & 1, n2 = Bb & 1;
            int row, col;
            if (mix == 0) { row = 2 * (t >> 2) + n1;          col = 4 * nw + 2 * ((t >> 1) & 1) + n2; }
            else          { row = 4 * nw + 2 * (t >> 6) + n1; col = 2 * ((t >> 1) & 31) + n2; }
            int pix = (b * 64 + row) * 64 + col;
            px[j] = pix;
            vst[t][j] = g_t[(size_t)pix * 32 + ch];
        }
        __syncthreads();
        float a0 = fbv, a1 = fbv, a2 = fbv, a3 = fbv;
        #pragma unroll 8
        for (int d = 0; d < 128; d++) {
            float4 vv = *(const float4*)&vst[d][0];
            float wv = Wsm[d][t];
            a0 += vv.x * wv; a1 += vv.y * wv; a2 += vv.z * wv; a3 += vv.w * wv;
        }
        g_mixed[(size_t)px[0] * 32 + ch] = a0;
        g_mixed[(size_t)px[1] * 32 + ch] = a1;
        g_mixed[(size_t)px[2] * 32 + ch] = a2;
        g_mixed[(size_t)px[3] * 32 + ch] = a3;
        __syncthreads();
    }
}

// ====================================================================
// K3: proj_out (both) + MixC + per-block partial sums (unchanged).
// ====================================================================
__global__ __launch_bounds__(512) void k3_combine(
    const float* __restrict__ x,
    const float* __restrict__ pout0, const float* __restrict__ pb0,
    const float* __restrict__ pout1, const float* __restrict__ pb1,
    const float* __restrict__ cwg, const float* __restrict__ cbg)
{
    __shared__ float msm[64][32];
    const int bx = blockIdx.x;
    const int b = bx >> 6, tile = bx & 63;
    const int ty = tile >> 3, tx = tile & 7;
    const int ch = threadIdx.x;

    for (int i = threadIdx.x; i < 2048; i += 512) {
        int pix = i >> 5, cc = i & 31;
        int pr = pix >> 3, pc = pix & 7;
        msm[pix][cc] = g_mixed[(size_t)((b*64 + ty*8 + pr) * 64 + tx*8 + pc) * 32 + cc];
    }
    __syncthreads();

    float w0r[16], w1r[16], cwr[16], cbr[4];
    #pragma unroll
    for (int k = 0; k < 16; k++) { w0r[k] = pout0[k*512 + ch]; w1r[k] = pout1[k*512 + ch]; }
    #pragma unroll
    for (int i = 0; i < 16; i++) cwr[i] = cwg[ch*16 + i];
    #pragma unroll
    for (int p = 0; p < 4; p++) cbr[p] = cbg[ch*4 + p];
    const float hb = pb0[ch], wb = pb1[ch];

    float ssum = 0.f;
    for (int bi = 0; bi < 16; bi++) {
        int brow = bi >> 2, bcol = bi & 3;
        int r0 = ty*8 + brow*2, c0 = tx*8 + bcol*2;
        float x4[4];
        #pragma unroll
        for (int q = 0; q < 4; q++) {
            int q1 = q >> 1, q2 = q & 1;
            x4[q] = x[(size_t)((b*64 + r0 + q1) * 64 + c0 + q2) * 512 + ch];
        }
        #pragma unroll
        for (int p = 0; p < 4; p++) {
            int p1 = p >> 1, p2 = p & 1;
            int pix = (brow*2 + p1) * 8 + (bcol*2 + p2);
            float cv = cbr[p];
            #pragma unroll
            for (int q = 0; q < 4; q++) cv += x4[q] * cwr[q*4 + p];

            const float4* m4 = (const float4*)&msm[pix][0];
            float4 m0 = m4[0], m1 = m4[1], m2 = m4[2], m3 = m4[3];
            float hv = hb;
            hv += m0.x*w0r[0]  + m0.y*w0r[1]  + m0.z*w0r[2]  + m0.w*w0r[3];
            hv += m1.x*w0r[4]  + m1.y*w0r[5]  + m1.z*w0r[6]  + m1.w*w0r[7];
            hv += m2.x*w0r[8]  + m2.y*w0r[9]  + m2.z*w0r[10] + m2.w*w0r[11];
            hv += m3.x*w0r[12] + m3.y*w0r[13] + m3.z*w0r[14] + m3.w*w0r[15];
            float4 u0 = m4[4], u1 = m4[5], u2 = m4[6], u3 = m4[7];
            float wv = wb;
            wv += u0.x*w1r[0]  + u0.y*w1r[1]  + u0.z*w1r[2]  + u0.w*w1r[3];
            wv += u1.x*w1r[4]  + u1.y*w1r[5]  + u1.z*w1r[6]  + u1.w*w1r[7];
            wv += u2.x*w1r[8]  + u2.y*w1r[9]  + u2.z*w1r[10] + u2.w*w1r[11];
            wv += u3.x*w1r[12] + u3.y*w1r[13] + u3.z*w1r[14] + u3.w*w1r[15];

            size_t gp = (size_t)((b*64 + r0 + p1) * 64 + c0 + p2) * 512 + ch;
            g_h[gp] = hv; g_w[gp] = wv; g_c[gp] = cv;
            ssum += hv + wv + cv;
        }
    }
    g_part[(size_t)bx * 512 + ch] = ssum;
}

// ====================================================================
// K4 (split): mean -> fc1+gelu -> fc2 -> softmax. Parallelized.
// ====================================================================
__global__ __launch_bounds__(512) void k4a_mean()
{
    const int b = blockIdx.x, c = threadIdx.x;
    float s = 0.f;
    #pragma unroll 8
    for (int tl = 0; tl < 64; tl++) s += g_part[(size_t)(b*64 + tl) * 512 + c];
    g_mean[b*512 + c] = s * (1.0f / 4096.0f);
}

__global__ __launch_bounds__(128) void k4b_fc1(
    const float* __restrict__ fc1w, const float* __restrict__ fc1b)
{
    __shared__ float asm_[512];
    const int b = blockIdx.x, t = threadIdx.x;
    for (int c = t; c < 512; c += 128) asm_[c] = g_mean[b*512 + c];
    __syncthreads();
    float acc = fc1b[t];
    #pragma unroll 8
    for (int k = 0; k < 512; k++) acc += asm_[k] * fc1w[k*128 + t];
    g_hid[b*128 + t] = 0.5f * acc * (1.0f + erff(acc * 0.70710678118654752f));
}

__global__ __launch_bounds__(128) void k4c_fc2(
    const float* __restrict__ fc2w, const float* __restrict__ fc2b)
{
    __shared__ float hsm[128];
    const int b = blockIdx.y, t = threadIdx.x;
    const int n = blockIdx.x * 128 + t;
    hsm[t] = g_hid[b*128 + t];
    __syncthreads();
    float acc = fc2b[n];
    #pragma unroll 8
    for (int j = 0; j < 128; j++) acc += hsm[j] * fc2w[j*1536 + n];
    g_f[b*1536 + n] = acc;
}

__global__ __launch_bounds__(512) void k4d_softmax()
{
    const int b = blockIdx.x, c = threadIdx.x;
    float v0 = g_f[b*1536 + c*3], v1 = g_f[b*1536 + c*3+1], v2 = g_f[b*1536 + c*3+2];
    float mx = fmaxf(v0, fmaxf(v1, v2));
    float e0 = expf(v0-mx), e1 = expf(v1-mx), e2 = expf(v2-mx);
    float inv = 1.0f / (e0 + e1 + e2);
    g_a3[(0*16 + b)*512 + c] = e0 * inv;
    g_a3[(1*16 + b)*512 + c] = e1 * inv;
    g_a3[(2*16 + b)*512 + c] = e2 * inv;
}

// ====================================================================
// K5: final fused GEMM: out = (h*a0 + w*a1 + c*a2) @ proj_w + proj_b.
// M=65536, N=512, K=512. 128x128 tiles, 256 threads, 8x8/thread.
// Packed f32x2 FMA + register prefetch of next k-slab.
// Grid (4, 512): N-tile fastest so the 4 blocks sharing an A slab are
// scheduled adjacently (L2 reuse of g_h/g_w/g_c).
// ====================================================================
__global__ __launch_bounds__(256) void k5_final(
    const float* __restrict__ pw, const float* __restrict__ pb,
    float* __restrict__ out)
{
    __shared__ float As[16][132];
    __shared__ float Bs[16][132];
    __shared__ float a3s[3][512];

    const int t = threadIdx.x;
    const int nbase = blockIdx.x * 128;
    const int mbase = blockIdx.y * 128;
    const int b = mbase >> 12;           // 4096 pixels per batch; tiles never straddle

    for (int i = t; i < 1536; i += 256) {
        int which = i / 512, kk = i % 512;
        a3s[which][kk] = g_a3[(which*16 + b)*512 + kk];
    }

    const int tr = t >> 4, tc = t & 15;      // 16x16 thread grid, 8x8 each
    const int pA = t >> 1, kA = (t & 1) * 8; // A-tile loader coords
    const int kB = t >> 4, nB = (t & 15) * 8;// B-tile loader coords

    unsigned long long acc2[8][4];
    #pragma unroll
    for (int i = 0; i < 8; i++)
        #pragma unroll
        for (int j = 0; j < 4; j++) acc2[i][j] = 0ull;

    // prefetch registers
    float4 rh[2], rw[2], rc[2], rb[2];
    {
        const size_t base = (size_t)(mbase + pA) * 512 + 0 + kA;
        #pragma unroll
        for (int h = 0; h < 2; h++) {
            rh[h] = *(const float4*)(g_h + base + h*4);
            rw[h] = *(const float4*)(g_w + base + h*4);
            rc[h] = *(const float4*)(g_c + base + h*4);
            rb[h] = *(const float4*)(pw + (size_t)(0 + kB) * 512 + nbase + nB + h*4);
        }
    }
    __syncthreads();   // a3s ready

    for (int k0 = 0; k0 < 512; k0 += 16) {
        // store prefetched regs -> smem (A combined with reweight coefs)
        #pragma unroll
        for (int h = 0; h < 2; h++) {
            int kb = k0 + kA + h*4;
            As[kA + h*4 + 0][pA] = rh[h].x*a3s[0][kb+0] + rw[h].x*a3s[1][kb+0] + rc[h].x*a3s[2][kb+0];
            As[kA + h*4 + 1][pA] = rh[h].y*a3s[0][kb+1] + rw[h].y*a3s[1][kb+1] + rc[h].y*a3s[2][kb+1];
            As[kA + h*4 + 2][pA] = rh[h].z*a3s[0][kb+2] + rw[h].z*a3s[1][kb+2] + rc[h].z*a3s[2][kb+2];
            As[kA + h*4 + 3][pA] = rh[h].w*a3s[0][kb+3] + rw[h].w*a3s[1][kb+3] + rc[h].w*a3s[2][kb+3];
            *(float4*)&Bs[kB][nB + h*4] = rb[h];
        }
        __syncthreads();

        // prefetch next slab while computing this one
        if (k0 + 16 < 512) {
            const size_t base = (size_t)(mbase + pA) * 512 + (k0 + 16) + kA;
            #pragma unroll
            for (int h = 0; h < 2; h++) {
                rh[h] = *(const float4*)(g_h + base + h*4);
                rw[h] = *(const float4*)(g_w + base + h*4);
                rc[h] = *(const float4*)(g_c + base + h*4);
                rb[h] = *(const float4*)(pw + (size_t)(k0 + 16 + kB) * 512 + nbase + nB + h*4);
            }
        }

        #pragma unroll
        for (int kk = 0; kk < 16; kk++) {
            float a_frag[8];
            *(float4*)&a_frag[0] = *(const float4*)&As[kk][tr*8];
            *(float4*)&a_frag[4] = *(const float4*)&As[kk][tr*8 + 4];
            const unsigned long long* bp = (const unsigned long long*)&Bs[kk][tc*8];
            unsigned long long b2[4];
            b2[0] = bp[0]; b2[1] = bp[1]; b2[2] = bp[2]; b2[3] = bp[3];
            #pragma unroll
            for (int i = 0; i < 8; i++) {
                unsigned long long aa;
                PACK2(aa, a_frag[i]);
                FMA_F32X2(acc2[i][0], aa, b2[0], acc2[i][0]);
                FMA_F32X2(acc2[i][1], aa, b2[1], acc2[i][1]);
                FMA_F32X2(acc2[i][2], aa, b2[2], acc2[i][2]);
                FMA_F32X2(acc2[i][3], aa, b2[3], acc2[i][3]);
            }
        }
        __syncthreads();
    }

    const int col0 = nbase + tc*8;
    float bias[8];
    #pragma unroll
    for (int j = 0; j < 8; j++) bias[j] = pb[col0 + j];
    #pragma unroll
    for (int i = 0; i < 8; i++) {
        float v[8];
        #pragma unroll
        for (int j = 0; j < 4; j++) UNPACK2(v[j*2], v[j*2+1], acc2[i][j]);
        size_t row = (size_t)(mbase + tr*8 + i);
        float4 o0 = make_float4(v[0]+bias[0], v[1]+bias[1], v[2]+bias[2], v[3]+bias[3]);
        float4 o1 = make_float4(v[4]+bias[4], v[5]+bias[5], v[6]+bias[6], v[7]+bias[7]);
        *(float4*)(out + row*512 + col0)     = o0;
        *(float4*)(out + row*512 + col0 + 4) = o1;
    }
}

// ====================================================================
extern "C" void kernel_launch(void* const* d_in, const int* in_sizes, int n_in,
                              void* d_out, int out_size)
{
    (void)in_sizes; (void)n_in; (void)out_size;
    const float* x       = (const float*)d_in[0];
    const float* mh_pinw = (const float*)d_in[1];
    const float* mh_pinb = (const float*)d_in[2];
    const float* mh_fw   = (const float*)d_in[3];
    const float* mh_fb   = (const float*)d_in[4];
    const float* mh_pow  = (const float*)d_in[5];
    const float* mh_pob  = (const float*)d_in[6];
    const float* mw_pinw = (const float*)d_in[7];
    const float* mw_pinb = (const float*)d_in[8];
    const float* mw_fw   = (const float*)d_in[9];
    const float* mw_fb   = (const float*)d_in[10];
    const float* mw_pow  = (const float*)d_in[11];
    const float* mw_pob  = (const float*)d_in[12];
    const float* c_w     = (const float*)d_in[13];
    const float* c_b     = (const float*)d_in[14];
    const float* fc1w    = (const float*)d_in[15];
    const float* fc1b    = (const float*)d_in[16];
    const float* fc2w    = (const float*)d_in[17];
    const float* fc2b    = (const float*)d_in[18];
    const float* projw   = (const float*)d_in[19];
    const float* projb   = (const float*)d_in[20];
    float* out = (float*)d_out;

    const int k2_smem = 128 * 129 * sizeof(float);  // 66048 B
    cudaFuncSetAttribute(k2_mix, cudaFuncAttributeMaxDynamicSharedMemorySize, k2_smem);

    k1_proj_in<<<512, 256>>>(x, mh_pinw, mh_pinb, mw_pinw, mw_pinb);
    k2_mix<<<256, 128, k2_smem>>>(mh_fw, mh_fb, mw_fw, mw_fb);
    k3_combine<<<1024, 512>>>(x, mh_pow, mh_pob, mw_pow, mw_pob, c_w, c_b);
    k4a_mean<<<16, 512>>>();
    k4b_fc1<<<16, 128>>>(fc1w, fc1b);
    k4c_fc2<<<dim3(12, 16), 128>>>(fc2w, fc2b);
    k4d_softmax<<<16, 512>>>();
    k5_final<<<dim3(4, 512), 256>>>(projw, projb, out);
}

// round 4
// speedup vs baseline: 1.7372x; 1.6892x over previous
#include <cuda_runtime.h>
#include <cuda_bf16.h>
#include <math.h>
#include <stdint.h>

// Problem dims
#define NPIX (16*64*64)      // 65536 pixels
#define DIMC 512

// -------- scratch (device globals; no allocations allowed) --------
__device__ __align__(16) float g_t[NPIX*32];
__device__ __align__(16) float g_mixed[NPIX*32];
__device__ __align__(16) float g_h[NPIX*DIMC];
__device__ __align__(16) float g_w[NPIX*DIMC];
__device__ __align__(16) float g_c[NPIX*DIMC];
__device__ __align__(16) float g_part[1024*DIMC];
__device__ __align__(16) float g_mean[16*DIMC];
__device__ __align__(16) float g_hid[16*128];
__device__ __align__(16) float g_f[16*1536];
__device__ __align__(16) float g_a3[3*16*DIMC];
// bf16 split planes for the tensor-core final GEMM
__device__ __align__(16) __nv_bfloat16 g_Ahi[NPIX*DIMC];
__device__ __align__(16) __nv_bfloat16 g_Alo[NPIX*DIMC];
__device__ __align__(16) __nv_bfloat16 g_Wt_hi[DIMC*DIMC];   // [n][k]
__device__ __align__(16) __nv_bfloat16 g_Wt_lo[DIMC*DIMC];

// ---------------- PTX helpers (portable sm_80+ subset) ----------------
__device__ __forceinline__ uint32_t smem_u32(const void* p) {
    uint32_t a;
    asm("{ .reg .u64 t; cvta.to.shared.u64 t, %1; cvt.u32.u64 %0, t; }" : "=r"(a) : "l"(p));
    return a;
}
#define CP_ASYNC16(dst, src) \
    asm volatile("cp.async.cg.shared.global [%0], [%1], 16;" :: "r"(dst), "l"(src))
#define CP_COMMIT() asm volatile("cp.async.commit_group;" ::: "memory")
#define CP_WAIT1()  asm volatile("cp.async.wait_group 1;" ::: "memory")
#define CP_WAIT0()  asm volatile("cp.async.wait_group 0;" ::: "memory")

#define LDMATRIX_X4(r0, r1, r2, r3, addr) \
    asm volatile("ldmatrix.sync.aligned.m8n8.x4.shared.b16 {%0,%1,%2,%3}, [%4];" \
                 : "=r"(r0), "=r"(r1), "=r"(r2), "=r"(r3) : "r"(addr))

#define MMA_BF16(c0, c1, c2, c3, a0, a1, a2, a3, b0, b1) \
    asm volatile("mma.sync.aligned.m16n8k16.row.col.f32.bf16.bf16.f32 " \
                 "{%0,%1,%2,%3}, {%4,%5,%6,%7}, {%8,%9}, {%0,%1,%2,%3};" \
                 : "+f"(c0), "+f"(c1), "+f"(c2), "+f"(c3) \
                 : "r"(a0), "r"(a1), "r"(a2), "r"(a3), "r"(b0), "r"(b1))

// packed fp32x2 FMA (kept in K1 only)
#define FMA_F32X2(d, a, b, c) \
    asm("fma.rn.f32x2 %0, %1, %2, %3;" : "=l"(d) : "l"(a), "l"(b), "l"(c))
#define PACK2(d, f) \
    asm("mov.b64 %0, {%1, %1};" : "=l"(d) : "f"(f))
#define UNPACK2(lo, hi, v) \
    asm("mov.b64 {%0, %1}, %2;" : "=f"(lo), "=f"(hi) : "l"(v))

// ====================================================================
// K1: fused proj_in for both branches.  GEMM M=65536, N=32, K=512.
// ====================================================================
__global__ __launch_bounds__(256) void k1_proj_in(
    const float* __restrict__ x,
    const float* __restrict__ w0, const float* __restrict__ b0,
    const float* __restrict__ w1, const float* __restrict__ b1)
{
    __shared__ float Xs[64][132];
    __shared__ float Ws[64][32];
    const int t = threadIdx.x;
    const int pbase = blockIdx.x * 128;
    const int p    = t >> 1;
    const int koff = (t & 1) * 32;
    const int tr = t >> 3;
    const int tc = t & 7;

    unsigned long long accp[4][2];
    #pragma unroll
    for (int r = 0; r < 4; r++) { accp[r][0] = 0ull; accp[r][1] = 0ull; }

    for (int kc = 0; kc < 512; kc += 64) {
        __syncthreads();
        #pragma unroll
        for (int i = 0; i < 8; i++) {
            float4 v = *(const float4*)(x + (size_t)(pbase + p) * 512 + kc + koff + i * 4);
            Xs[koff + i*4 + 0][p] = v.x;
            Xs[koff + i*4 + 1][p] = v.y;
            Xs[koff + i*4 + 2][p] = v.z;
            Xs[koff + i*4 + 3][p] = v.w;
        }
        #pragma unroll
        for (int i = 0; i < 8; i++) {
            int idx = t + i * 256;
            int k = idx >> 5, j = idx & 31;
            Ws[k][j] = (j < 16) ? w0[(kc + k) * 16 + j] : w1[(kc + k) * 16 + (j - 16)];
        }
        __syncthreads();
        #pragma unroll
        for (int kk = 0; kk < 64; kk++) {
            float4 av = *(const float4*)&Xs[kk][tr * 4];
            const unsigned long long* bp = (const unsigned long long*)&Ws[kk][tc * 4];
            unsigned long long b20 = bp[0], b21 = bp[1];
            unsigned long long aa;
            PACK2(aa, av.x); FMA_F32X2(accp[0][0], aa, b20, accp[0][0]); FMA_F32X2(accp[0][1], aa, b21, accp[0][1]);
            PACK2(aa, av.y); FMA_F32X2(accp[1][0], aa, b20, accp[1][0]); FMA_F32X2(accp[1][1], aa, b21, accp[1][1]);
            PACK2(aa, av.z); FMA_F32X2(accp[2][0], aa, b20, accp[2][0]); FMA_F32X2(accp[2][1], aa, b21, accp[2][1]);
            PACK2(aa, av.w); FMA_F32X2(accp[3][0], aa, b20, accp[3][0]); FMA_F32X2(accp[3][1], aa, b21, accp[3][1]);
        }
    }
    float bb[4];
    #pragma unroll
    for (int j = 0; j < 4; j++) { int c = tc*4 + j; bb[j] = (c < 16) ? b0[c] : b1[c - 16]; }

    #pragma unroll
    for (int r = 0; r < 4; r++) {
        float v0, v1, v2, v3;
        UNPACK2(v0, v1, accp[r][0]);
        UNPACK2(v2, v3, accp[r][1]);
        float4 o = make_float4(v0+bb[0], v1+bb[1], v2+bb[2], v3+bb[3]);
        *(float4*)(g_t + (size_t)(pbase + tr*4 + r) * 32 + tc*4) = o;
    }
}

// ====================================================================
// K2: windowed mixing for both branches.
// ====================================================================
__global__ __launch_bounds__(128) void k2_mix(
    const float* __restrict__ fw0, const float* __restrict__ fb0,
    const float* __restrict__ fw1, const float* __restrict__ fb1)
{
    extern __shared__ float sm[];
    float (*Wsm)[129] = (float (*)[129])sm;
    __shared__ float vst[128][4];

    const int mix  = blockIdx.x >> 7;
    const int head = (blockIdx.x >> 4) & 7;
    const int wt   = blockIdx.x & 15;
    const float* fw = mix ? fw1 : fw0;
    const float* fb = mix ? fb1 : fb0;
    const int t = threadIdx.x;

    for (int i = t; i < 128 * 128; i += 128) {
        int d = i & 127;
        int f = i >> 7;
        Wsm[d][f] = fw[f * 1024 + head * 128 + d];
    }
    const int ch = mix * 16 + head * 2 + (t & 1);
    const float fbv = fb[t];
    __syncthreads();

    for (int pass = 0; pass < 16; pass++) {
        int px[4];
        #pragma unroll
        for (int j = 0; j < 4; j++) {
            int wg = wt * 64 + pass * 4 + j;
            int Bb = wg >> 4, nw = wg & 15;
            int b = Bb >> 2, n1 = (Bb >> 1) & 1, n2 = Bb & 1;
            int row, col;
            if (mix == 0) { row = 2 * (t >> 2) + n1;          col = 4 * nw + 2 * ((t >> 1) & 1) + n2; }
            else          { row = 4 * nw + 2 * (t >> 6) + n1; col = 2 * ((t >> 1) & 31) + n2; }
            int pix = (b * 64 + row) * 64 + col;
            px[j] = pix;
            vst[t][j] = g_t[(size_t)pix * 32 + ch];
        }
        __syncthreads();
        float a0 = fbv, a1 = fbv, a2 = fbv, a3 = fbv;
        #pragma unroll 8
        for (int d = 0; d < 128; d++) {
            float4 vv = *(const float4*)&vst[d][0];
            float wv = Wsm[d][t];
            a0 += vv.x * wv; a1 += vv.y * wv; a2 += vv.z * wv; a3 += vv.w * wv;
        }
        g_mixed[(size_t)px[0] * 32 + ch] = a0;
        g_mixed[(size_t)px[1] * 32 + ch] = a1;
        g_mixed[(size_t)px[2] * 32 + ch] = a2;
        g_mixed[(size_t)px[3] * 32 + ch] = a3;
        __syncthreads();
    }
}

// ====================================================================
// K3: proj_out (both) + MixC + per-block partial sums.
// ====================================================================
__global__ __launch_bounds__(512) void k3_combine(
    const float* __restrict__ x,
    const float* __restrict__ pout0, const float* __restrict__ pb0,
    const float* __restrict__ pout1, const float* __restrict__ pb1,
    const float* __restrict__ cwg, const float* __restrict__ cbg)
{
    __shared__ float msm[64][32];
    const int bx = blockIdx.x;
    const int b = bx >> 6, tile = bx & 63;
    const int ty = tile >> 3, tx = tile & 7;
    const int ch = threadIdx.x;

    for (int i = threadIdx.x; i < 2048; i += 512) {
        int pix = i >> 5, cc = i & 31;
        int pr = pix >> 3, pc = pix & 7;
        msm[pix][cc] = g_mixed[(size_t)((b*64 + ty*8 + pr) * 64 + tx*8 + pc) * 32 + cc];
    }
    __syncthreads();

    float w0r[16], w1r[16], cwr[16], cbr[4];
    #pragma unroll
    for (int k = 0; k < 16; k++) { w0r[k] = pout0[k*512 + ch]; w1r[k] = pout1[k*512 + ch]; }
    #pragma unroll
    for (int i = 0; i < 16; i++) cwr[i] = cwg[ch*16 + i];
    #pragma unroll
    for (int p = 0; p < 4; p++) cbr[p] = cbg[ch*4 + p];
    const float hb = pb0[ch], wb = pb1[ch];

    float ssum = 0.f;
    for (int bi = 0; bi < 16; bi++) {
        int brow = bi >> 2, bcol = bi & 3;
        int r0 = ty*8 + brow*2, c0 = tx*8 + bcol*2;
        float x4[4];
        #pragma unroll
        for (int q = 0; q < 4; q++) {
            int q1 = q >> 1, q2 = q & 1;
            x4[q] = x[(size_t)((b*64 + r0 + q1) * 64 + c0 + q2) * 512 + ch];
        }
        #pragma unroll
        for (int p = 0; p < 4; p++) {
            int p1 = p >> 1, p2 = p & 1;
            int pix = (brow*2 + p1) * 8 + (bcol*2 + p2);
            float cv = cbr[p];
            #pragma unroll
            for (int q = 0; q < 4; q++) cv += x4[q] * cwr[q*4 + p];

            const float4* m4 = (const float4*)&msm[pix][0];
            float4 m0 = m4[0], m1 = m4[1], m2 = m4[2], m3 = m4[3];
            float hv = hb;
            hv += m0.x*w0r[0]  + m0.y*w0r[1]  + m0.z*w0r[2]  + m0.w*w0r[3];
            hv += m1.x*w0r[4]  + m1.y*w0r[5]  + m1.z*w0r[6]  + m1.w*w0r[7];
            hv += m2.x*w0r[8]  + m2.y*w0r[9]  + m2.z*w0r[10] + m2.w*w0r[11];
            hv += m3.x*w0r[12] + m3.y*w0r[13] + m3.z*w0r[14] + m3.w*w0r[15];
            float4 u0 = m4[4], u1 = m4[5], u2 = m4[6], u3 = m4[7];
            float wv = wb;
            wv += u0.x*w1r[0]  + u0.y*w1r[1]  + u0.z*w1r[2]  + u0.w*w1r[3];
            wv += u1.x*w1r[4]  + u1.y*w1r[5]  + u1.z*w1r[6]  + u1.w*w1r[7];
            wv += u2.x*w1r[8]  + u2.y*w1r[9]  + u2.z*w1r[10] + u2.w*w1r[11];
            wv += u3.x*w1r[12] + u3.y*w1r[13] + u3.z*w1r[14] + u3.w*w1r[15];

            size_t gp = (size_t)((b*64 + r0 + p1) * 64 + c0 + p2) * 512 + ch;
            g_h[gp] = hv; g_w[gp] = wv; g_c[gp] = cv;
            ssum += hv + wv + cv;
        }
    }
    g_part[(size_t)bx * 512 + ch] = ssum;
}

// ====================================================================
// K4 (split): mean -> fc1+gelu -> fc2 -> softmax.
// ====================================================================
__global__ __launch_bounds__(512) void k4a_mean()
{
    const int b = blockIdx.x, c = threadIdx.x;
    float s = 0.f;
    #pragma unroll 8
    for (int tl = 0; tl < 64; tl++) s += g_part[(size_t)(b*64 + tl) * 512 + c];
    g_mean[b*512 + c] = s * (1.0f / 4096.0f);
}

__global__ __launch_bounds__(128) void k4b_fc1(
    const float* __restrict__ fc1w, const float* __restrict__ fc1b)
{
    __shared__ float asm_[512];
    const int b = blockIdx.x, t = threadIdx.x;
    for (int c = t; c < 512; c += 128) asm_[c] = g_mean[b*512 + c];
    __syncthreads();
    float acc = fc1b[t];
    #pragma unroll 8
    for (int k = 0; k < 512; k++) acc += asm_[k] * fc1w[k*128 + t];
    g_hid[b*128 + t] = 0.5f * acc * (1.0f + erff(acc * 0.70710678118654752f));
}

__global__ __launch_bounds__(128) void k4c_fc2(
    const float* __restrict__ fc2w, const float* __restrict__ fc2b)
{
    __shared__ float hsm[128];
    const int b = blockIdx.y, t = threadIdx.x;
    const int n = blockIdx.x * 128 + t;
    hsm[t] = g_hid[b*128 + t];
    __syncthreads();
    float acc = fc2b[n];
    #pragma unroll 8
    for (int j = 0; j < 128; j++) acc += hsm[j] * fc2w[j*1536 + n];
    g_f[b*1536 + n] = acc;
}

__global__ __launch_bounds__(512) void k4d_softmax()
{
    const int b = blockIdx.x, c = threadIdx.x;
    float v0 = g_f[b*1536 + c*3], v1 = g_f[b*1536 + c*3+1], v2 = g_f[b*1536 + c*3+2];
    float mx = fmaxf(v0, fmaxf(v1, v2));
    float e0 = expf(v0-mx), e1 = expf(v1-mx), e2 = expf(v2-mx);
    float inv = 1.0f / (e0 + e1 + e2);
    g_a3[(0*16 + b)*512 + c] = e0 * inv;
    g_a3[(1*16 + b)*512 + c] = e1 * inv;
    g_a3[(2*16 + b)*512 + c] = e2 * inv;
}

// ====================================================================
// K5w: transpose + bf16 hi/lo split of proj_w. g_Wt[n][k].
// ====================================================================
__global__ __launch_bounds__(256) void k5w_prep(const float* __restrict__ pw)
{
    const int k = blockIdx.x >> 1;
    const int n = ((blockIdx.x & 1) << 8) + threadIdx.x;
    float v = pw[k*512 + n];
    __nv_bfloat16 hi = __float2bfloat16(v);
    float lo = v - __bfloat162float(hi);
    g_Wt_hi[(size_t)n*512 + k] = hi;
    g_Wt_lo[(size_t)n*512 + k] = __float2bfloat16(lo);
}

// ====================================================================
// K5a: A = h*a0 + w*a1 + c*a2, split into bf16 hi/lo planes.
// ====================================================================
__global__ __launch_bounds__(256) void k5a_combine()
{
    const size_t gid = (size_t)blockIdx.x * 256 + threadIdx.x;
    const int p  = (int)(gid >> 7);
    const int kq = ((int)gid & 127) << 2;
    const int b  = p >> 12;
    const size_t off = (size_t)p * 512 + kq;

    float4 h = *(const float4*)(g_h + off);
    float4 w = *(const float4*)(g_w + off);
    float4 c = *(const float4*)(g_c + off);
    float4 A0 = *(const float4*)(g_a3 + (size_t)(0*16 + b)*512 + kq);
    float4 A1 = *(const float4*)(g_a3 + (size_t)(1*16 + b)*512 + kq);
    float4 A2 = *(const float4*)(g_a3 + (size_t)(2*16 + b)*512 + kq);

    float a[4];
    a[0] = h.x*A0.x + w.x*A1.x + c.x*A2.x;
    a[1] = h.y*A0.y + w.y*A1.y + c.y*A2.y;
    a[2] = h.z*A0.z + w.z*A1.z + c.z*A2.z;
    a[3] = h.w*A0.w + w.w*A1.w + c.w*A2.w;

    __nv_bfloat16 hi[4], lo[4];
    #pragma unroll
    for (int j = 0; j < 4; j++) {
        hi[j] = __float2bfloat16(a[j]);
        lo[j] = __float2bfloat16(a[j] - __bfloat162float(hi[j]));
    }
    __nv_bfloat162* dh = (__nv_bfloat162*)(g_Ahi + off);
    __nv_bfloat162* dl = (__nv_bfloat162*)(g_Alo + off);
    dh[0] = __halves2bfloat162(hi[0], hi[1]);
    dh[1] = __halves2bfloat162(hi[2], hi[3]);
    dl[0] = __halves2bfloat162(lo[0], lo[1]);
    dl[1] = __halves2bfloat162(lo[2], lo[3]);
}

// ====================================================================
// K5b: HMMA (mma.sync bf16) split-precision GEMM.
// out[M=65536, N=512] = A @ Wt^T, 3 passes: AhBh + AhBl + AlBh, fp32 acc.
// CTA tile 128M x 256N, 8 warps of 64x64. K chunks of 32, 2-stage cp.async.
// Stage layout (48KB): Ah[128][32] @0 | Al @8K | Bh[256][32] @16K | Bl @32K.
// Rows 64B = 4x16B chunks, swizzle chunk^=(row>>1)&3 (bank-conflict-free
// for ldmatrix: bank = 4*chunk + 16*(row&1), distinct over 8 rows).
// ====================================================================
#define K5B_STAGE 49152u

__global__ __launch_bounds__(256, 1) void k5b_gemm(
    const float* __restrict__ pb, float* __restrict__ out)
{
    extern __shared__ char dsm[];
    const uint32_t base = smem_u32(dsm);

    const int tid  = threadIdx.x;
    const int wid  = tid >> 5;
    const int lane = tid & 31;
    const int nbase = blockIdx.x * 256;
    const int mbase = blockIdx.y * 128;
    const int wm = (wid >> 2) * 64;   // warp M offset (0/64)
    const int wn = (wid & 3) * 64;    // warp N offset (0/64/128/192)

    float acc[4][8][4];
    #pragma unroll
    for (int i = 0; i < 4; i++)
        #pragma unroll
        for (int j = 0; j < 8; j++)
            #pragma unroll
            for (int q = 0; q < 4; q++) acc[i][j][q] = 0.f;

    // ---- stage fill via cp.async ----
    auto fill = [&](int s, int ch) {
        const uint32_t st = base + (uint32_t)s * K5B_STAGE;
        const int k0 = ch * 32;
        #pragma unroll
        for (int r = 0; r < 2; r++) {            // A planes: 512 chunks each
            int idx = tid + r * 256;
            int row = idx >> 2, c = idx & 3;
            uint32_t dst = st + row * 64 + (((c ^ (row >> 1)) & 3) << 4);
            const char* sh = (const char*)(g_Ahi + (size_t)(mbase + row) * 512 + k0) + c * 16;
            const char* sl = (const char*)(g_Alo + (size_t)(mbase + row) * 512 + k0) + c * 16;
            CP_ASYNC16(dst, sh);
            CP_ASYNC16(dst + 8192u, sl);
        }
        #pragma unroll
        for (int r = 0; r < 4; r++) {            // B planes: 1024 chunks each
            int idx = tid + r * 256;
            int row = idx >> 2, c = idx & 3;
            uint32_t dst = st + 16384u + row * 64 + (((c ^ (row >> 1)) & 3) << 4);
            const char* sh = (const char*)(g_Wt_hi + (size_t)(nbase + row) * 512 + k0) + c * 16;
            const char* sl = (const char*)(g_Wt_lo + (size_t)(nbase + row) * 512 + k0) + c * 16;
            CP_ASYNC16(dst, sh);
            CP_ASYNC16(dst + 16384u, sl);
        }
        CP_COMMIT();
    };

    fill(0, 0);
    fill(1, 1);

    for (int ch = 0; ch < 16; ch++) {
        const int s = ch & 1;
        const uint32_t st = base + (uint32_t)s * K5B_STAGE;
        if (ch < 14) { CP_WAIT1(); } else { CP_WAIT0(); }
        __syncthreads();

        #pragma unroll
        for (int pass = 0; pass < 3; pass++) {
            const uint32_t Aoff = st + (pass == 2 ? 8192u : 0u);
            const uint32_t Boff = st + 16384u + (pass == 1 ? 16384u : 0u);
            #pragma unroll
            for (int kk = 0; kk < 2; kk++) {
                const int cbase = 2 * kk + (lane >> 4);   // logical chunk for this lane
                uint32_t a[4][4];
                #pragma unroll
                for (int i = 0; i < 4; i++) {
                    int row = wm + i * 16 + (lane & 15);
                    uint32_t ad = Aoff + row * 64 + (((cbase ^ (row >> 1)) & 3) << 4);
                    LDMATRIX_X4(a[i][0], a[i][1], a[i][2], a[i][3], ad);
                }
                uint32_t b[8][2];
                #pragma unroll
                for (int j = 0; j < 4; j++) {
                    int row = wn + j * 16 + (lane & 15);
                    uint32_t bd = Boff + row * 64 + (((cbase ^ (row >> 1)) & 3) << 4);
                    uint32_t r0, r1, r2, r3;
                    LDMATRIX_X4(r0, r1, r2, r3, bd);
                    b[2*j][0] = r0;   b[2*j][1] = r2;
                    b[2*j+1][0] = r1; b[2*j+1][1] = r3;
                }
                #pragma unroll
                for (int i = 0; i < 4; i++)
                    #pragma unroll
                    for (int j = 0; j < 8; j++)
                        MMA_BF16(acc[i][j][0], acc[i][j][1], acc[i][j][2], acc[i][j][3],
                                 a[i][0], a[i][1], a[i][2], a[i][3],
                                 b[j][0], b[j][1]);
            }
        }
        __syncthreads();
        if (ch + 2 < 16) fill(s, ch + 2);
    }

    // ---- epilogue: C frag (t/4 row, (t%4)*2 col; +8 row for c2,c3) ----
    #pragma unroll
    for (int i = 0; i < 4; i++) {
        const int r0 = mbase + wm + i * 16 + (lane >> 2);
        #pragma unroll
        for (int j = 0; j < 8; j++) {
            const int col = nbase + wn + j * 8 + (lane & 3) * 2;
            const float2 bb = *(const float2*)(pb + col);
            float2 o0 = make_float2(acc[i][j][0] + bb.x, acc[i][j][1] + bb.y);
            float2 o1 = make_float2(acc[i][j][2] + bb.x, acc[i][j][3] + bb.y);
            *(float2*)(out + (size_t)r0 * 512 + col)       = o0;
            *(float2*)(out + (size_t)(r0 + 8) * 512 + col) = o1;
        }
    }
}

// ====================================================================
extern "C" void kernel_launch(void* const* d_in, const int* in_sizes, int n_in,
                              void* d_out, int out_size)
{
    (void)in_sizes; (void)n_in; (void)out_size;
    const float* x       = (const float*)d_in[0];
    const float* mh_pinw = (const float*)d_in[1];
    const float* mh_pinb = (const float*)d_in[2];
    const float* mh_fw   = (const float*)d_in[3];
    const float* mh_fb   = (const float*)d_in[4];
    const float* mh_pow  = (const float*)d_in[5];
    const float* mh_pob  = (const float*)d_in[6];
    const float* mw_pinw = (const float*)d_in[7];
    const float* mw_pinb = (const float*)d_in[8];
    const float* mw_fw   = (const float*)d_in[9];
    const float* mw_fb   = (const float*)d_in[10];
    const float* mw_pow  = (const float*)d_in[11];
    const float* mw_pob  = (const float*)d_in[12];
    const float* c_w     = (const float*)d_in[13];
    const float* c_b     = (const float*)d_in[14];
    const float* fc1w    = (const float*)d_in[15];
    const float* fc1b    = (const float*)d_in[16];
    const float* fc2w    = (const float*)d_in[17];
    const float* fc2b    = (const float*)d_in[18];
    const float* projw   = (const float*)d_in[19];
    const float* projb   = (const float*)d_in[20];
    float* out = (float*)d_out;

    const int k2_smem  = 128 * 129 * sizeof(float);   // 66048 B
    const int k5b_smem = 2 * (int)K5B_STAGE;          // 98304 B
    cudaFuncSetAttribute(k2_mix,   cudaFuncAttributeMaxDynamicSharedMemorySize, k2_smem);
    cudaFuncSetAttribute(k5b_gemm, cudaFuncAttributeMaxDynamicSharedMemorySize, k5b_smem);

    k1_proj_in<<<512, 256>>>(x, mh_pinw, mh_pinb, mw_pinw, mw_pinb);
    k2_mix<<<256, 128, k2_smem>>>(mh_fw, mh_fb, mw_fw, mw_fb);
    k3_combine<<<1024, 512>>>(x, mh_pow, mh_pob, mw_pow, mw_pob, c_w, c_b);
    k4a_mean<<<16, 512>>>();
    k4b_fc1<<<16, 128>>>(fc1w, fc1b);
    k4c_fc2<<<dim3(12, 16), 128>>>(fc2w, fc2b);
    k4d_softmax<<<16, 512>>>();
    k5w_prep<<<1024, 256>>>(projw);
    k5a_combine<<<32768, 256>>>();
    k5b_gemm<<<dim3(2, 512), 256, k5b_smem>>>(projb, out);
}